// round 17
// baseline (speedup 1.0000x reference)
#include <cuda_runtime.h>
#include <float.h>
#include <stdint.h>

#define BB 2
#define HH 12
#define NN 1600
#define DD 32
#define GG 48
#define KT 96
#define CC 384
#define BHc (BB*HH)          // 24
#define NQ (BHc*NN)          // 38400
#define NROW (BHc*GG)        // 1152

// Scratch (no cudaMalloc allowed)
__device__ float g_qkv[3][BHc*NN*DD];      // [which][b*h][n][d]
__device__ int   g_gidx[NQ];
__device__ float g_qsum[NROW*DD];
__device__ int   g_cnt[NROW];
__device__ int   g_qlist[NROW*NN];         // query indices per (bh,g)
__device__ float g_att[BB*NN*HH*DD];       // [b][n][h][d]
__device__ unsigned g_scores[NROW*NN];     // f2u-mapped qmw scores

// ---------------- 3xTF32 mma.sync GEMM (R7 math, (256,2) occupancy) ----------
__device__ __forceinline__ uint32_t tf32_rna(float x) {
    uint32_t r; asm("cvt.rna.tf32.f32 %0, %1;" : "=r"(r) : "f"(x)); return r;
}
__device__ __forceinline__ void split_tf32(float x, uint32_t& h, uint32_t& l) {
    h = tf32_rna(x);
    l = tf32_rna(x - __uint_as_float(h));
}
__device__ __forceinline__ void mma8(float* c, const uint32_t* a, const uint32_t* b) {
    asm volatile(
        "mma.sync.aligned.m16n8k8.row.col.f32.tf32.tf32.f32 "
        "{%0,%1,%2,%3}, {%4,%5,%6,%7}, {%8,%9}, {%0,%1,%2,%3};"
        : "+f"(c[0]), "+f"(c[1]), "+f"(c[2]), "+f"(c[3])
        : "r"(a[0]), "r"(a[1]), "r"(a[2]), "r"(a[3]), "r"(b[0]), "r"(b[1]));
}

// out[m][col] = sum_k A[m][k] * B[col][k]   (NT, K=384)
// MODE 0: A = x, scatter into g_qkv; also zero-inits g_qsum/g_cnt.
// MODE 1: A = g_att, write d_out.
template<int MODE>
__global__ void __launch_bounds__(256, 2) gemm_tf32(const float* __restrict__ A,
                                                    const float* __restrict__ B,
                                                    float* __restrict__ out) {
    __shared__ __align__(16) float As[128][36];
    __shared__ __align__(16) float Bs[128][36];
    const int K = CC;
    const float* Ap = (MODE == 0) ? A : (const float*)g_att;
    int m0 = blockIdx.y * 128, n0 = blockIdx.x * 128;
    int tid = threadIdx.x, wid = tid >> 5, lane = tid & 31;
    int warpM = (wid >> 2) * 64;
    int warpN = (wid & 3) * 32;

    if (MODE == 0) {
        int zi = (blockIdx.y * 9 + blockIdx.x) * 256 + tid;
        if (zi < NROW*DD) g_qsum[zi] = 0.f;
        if (zi < NROW)    g_cnt[zi] = 0;
    }

    float acc[4][4][4];
    #pragma unroll
    for (int i = 0; i < 4; i++)
        #pragma unroll
        for (int j = 0; j < 4; j++)
            #pragma unroll
            for (int r = 0; r < 4; r++) acc[i][j][r] = 0.f;

    int srow = tid >> 3, sc4 = (tid & 7) << 2;
    for (int kt = 0; kt < K/32; kt++) {
        int k0 = kt * 32;
        #pragma unroll
        for (int it = 0; it < 4; it++) {
            int row = it*32 + srow;
            float4 va = *(const float4*)(Ap + (size_t)(m0 + row)*K + k0 + sc4);
            float4 vb = *(const float4*)(B  + (size_t)(n0 + row)*K + k0 + sc4);
            *(float4*)&As[row][sc4] = va;
            *(float4*)&Bs[row][sc4] = vb;
        }
        __syncthreads();
        #pragma unroll
        for (int kk = 0; kk < 4; kk++) {
            int c = kk*8 + (lane & 3);
            uint32_t ah[4][4], al[4][4], bh[4][2], bl[4][2];
            #pragma unroll
            for (int fm = 0; fm < 4; fm++) {
                int r = warpM + fm*16 + (lane >> 2);
                split_tf32(As[r    ][c    ], ah[fm][0], al[fm][0]);
                split_tf32(As[r + 8][c    ], ah[fm][1], al[fm][1]);
                split_tf32(As[r    ][c + 4], ah[fm][2], al[fm][2]);
                split_tf32(As[r + 8][c + 4], ah[fm][3], al[fm][3]);
            }
            #pragma unroll
            for (int fn = 0; fn < 4; fn++) {
                int n = warpN + fn*8 + (lane >> 2);
                split_tf32(Bs[n][c    ], bh[fn][0], bl[fn][0]);
                split_tf32(Bs[n][c + 4], bh[fn][1], bl[fn][1]);
            }
            #pragma unroll
            for (int fm = 0; fm < 4; fm++)
                #pragma unroll
                for (int fn = 0; fn < 4; fn++)
                    mma8(acc[fm][fn], ah[fm], bh[fn]);
            #pragma unroll
            for (int fm = 0; fm < 4; fm++)
                #pragma unroll
                for (int fn = 0; fn < 4; fn++)
                    mma8(acc[fm][fn], ah[fm], bl[fn]);
            #pragma unroll
            for (int fm = 0; fm < 4; fm++)
                #pragma unroll
                for (int fn = 0; fn < 4; fn++)
                    mma8(acc[fm][fn], al[fm], bh[fn]);
        }
        __syncthreads();
    }

    #pragma unroll
    for (int fm = 0; fm < 4; fm++) {
        #pragma unroll
        for (int half = 0; half < 2; half++) {
            int m = m0 + warpM + fm*16 + (lane >> 2) + half*8;
            int bi = m / NN, n = m % NN;
            #pragma unroll
            for (int fn = 0; fn < 4; fn++) {
                int col = n0 + warpN + fn*8 + 2*(lane & 3);
                float v0 = acc[fm][fn][half*2 + 0];
                float v1 = acc[fm][fn][half*2 + 1];
                if (MODE == 0) {
                    int which = col / (HH*DD);
                    int r2 = col % (HH*DD);
                    int head = r2 / DD, dd = r2 % DD;
                    float* dst = &g_qkv[which][(((size_t)bi*HH + head)*NN + n)*DD + dd];
                    *(float2*)dst = make_float2(v0, v1);
                } else {
                    *(float2*)&out[(size_t)m*(HH*DD) + col] = make_float2(v0, v1);
                }
            }
        }
    }
}

// 32 queries per block (4 per warp). Lane-per-group argmax via LDS.128
// broadcast (FFMA order bit-identical to the sequential d-loop: separate
// statements prevent reassociation). First-max tie-break = jnp.argmax.
__global__ void route_kernel(const float* __restrict__ w_gp) {
    __shared__ __align__(16) float sgp[GG][36];
    __shared__ __align__(16) float q_s[8][36];
    int tid = threadIdx.x;
    int w = tid >> 5, lane = tid & 31;
    int q0 = blockIdx.x * 32;          // NN % 32 == 0 -> whole block same bh
    int bh = q0 / NN;
    int h = bh % HH;
    for (int i = tid; i < GG*DD; i += 256)
        sgp[i >> 5][i & 31] = w_gp[h*GG*DD + i];
    __syncthreads();
    #pragma unroll
    for (int rep = 0; rep < 4; rep++) {
        int qid = q0 + rep*8 + w;
        int n = qid % NN;
        float qv = g_qkv[0][((size_t)bh*NN + n)*DD + lane];
        q_s[w][lane] = qv;
        __syncwarp();
        float s0 = 0.f, s1 = 0.f;
        #pragma unroll
        for (int t = 0; t < 8; t++) {
            float4 q4 = *(const float4*)&q_s[w][4*t];
            float4 g0 = *(const float4*)&sgp[lane][4*t];
            s0 += q4.x*g0.x; s0 += q4.y*g0.y; s0 += q4.z*g0.z; s0 += q4.w*g0.w;
            if (lane < 16) {
                float4 g1 = *(const float4*)&sgp[lane + 32][4*t];
                s1 += q4.x*g1.x; s1 += q4.y*g1.y; s1 += q4.z*g1.z; s1 += q4.w*g1.w;
            }
        }
        float bv = s0; int bg = lane;
        if (lane < 16 && (s1 > bv)) { bv = s1; bg = lane + 32; }
        #pragma unroll
        for (int o = 16; o; o >>= 1) {
            float ov = __shfl_xor_sync(0xffffffffu, bv, o);
            int   og = __shfl_xor_sync(0xffffffffu, bg, o);
            if (ov > bv || (ov == bv && og < bg)) { bv = ov; bg = og; }
        }
        bg = __shfl_sync(0xffffffffu, bg, 0);
        int row = bh*GG + bg;
        if (lane == 0) {
            g_gidx[qid] = bg;
            int p = atomicAdd(&g_cnt[row], 1);
            g_qlist[row*NN + p] = n;
        }
        atomicAdd(&g_qsum[row*DD + lane], qv);
        __syncwarp();                  // q_s reuse across reps
    }
}

__device__ __forceinline__ unsigned f2u_mono(float f) {
    unsigned u = __float_as_uint(f);
    return u ^ (((int)u >> 31) | 0x80000000u);
}

// Grid (25, BHc): 64 keys per block; thread = (key, 12-group chunk).
__global__ void qmw_score_kernel() {
    __shared__ __align__(16) float qm[GG][DD];
    int bh = blockIdx.y;
    int n0 = blockIdx.x * 64;
    int tid = threadIdx.x;
    for (int i = tid; i < GG*DD; i += 256) {
        int g = i >> 5, d = i & 31;
        int row = bh*GG + g;
        float c = (float)g_cnt[row];
        qm[g][d] = g_qsum[row*DD + d] / fmaxf(c, 1e-8f);
    }
    __syncthreads();
    int key = tid & 63, gc = (tid >> 6) * 12;
    int m = n0 + key;
    const float* kb = &g_qkv[1][(size_t)bh*NN*DD];
    float kr[DD];
    #pragma unroll
    for (int t = 0; t < 8; t++) {
        float4 v = *(const float4*)(kb + (size_t)m*DD + 4*t);
        kr[4*t] = v.x; kr[4*t+1] = v.y; kr[4*t+2] = v.z; kr[4*t+3] = v.w;
    }
    float s[12];
    #pragma unroll
    for (int j = 0; j < 12; j++) s[j] = 0.f;
    #pragma unroll
    for (int t = 0; t < 8; t++) {
        #pragma unroll
        for (int j = 0; j < 12; j++) {
            float4 q = *(const float4*)&qm[gc + j][4*t];
            s[j] += q.x*kr[4*t] + q.y*kr[4*t+1] + q.z*kr[4*t+2] + q.w*kr[4*t+3];
        }
    }
    #pragma unroll
    for (int j = 0; j < 12; j++)
        g_scores[(size_t)(bh*GG + gc + j)*NN + m] = f2u_mono(s[j]);
}

// Fused: one block per (bh,g) row — radix-select top-96 (R15 plain 4-pass),
// then stage K (key-major) + V (d-major) and run attention 4-queries-per-warp.
// ublk aliases: selection-phase uv[NN] vs attention-phase q/p buffers.
#define QS_BYTES (8*4*36*4)    // 4608
#define PS_BYTES (8*4*100*4)   // 12800
__global__ void select_attn_kernel() {
    int row = blockIdx.x;              // [0, NROW)
    int cnt = g_cnt[row];
    if (cnt == 0) return;

    __shared__ unsigned hist[256];
    __shared__ int s_selb, s_k, s_nout;
    __shared__ int warp_sums[8];
    __shared__ int tk_s[KT];
    __shared__ __align__(16) float Kr[KT][36];   // [key][d]
    __shared__ __align__(16) float Vt[DD][100];  // [d][key]
    __shared__ __align__(16) char ublk[QS_BYTES + PS_BYTES];  // uv | q_s+p_s

    unsigned* uv = (unsigned*)ublk;              // NN*4 = 6400 <= 17408

    int tid = threadIdx.x, lane = tid & 31, w = tid >> 5;

    // ---- selection phase ----
    const unsigned* src = &g_scores[(size_t)row*NN];
    for (int m = tid; m < NN; m += 256) uv[m] = src[m];
    hist[tid] = 0;
    __syncthreads();

    unsigned prefix = 0;
    int k = KT;
    #pragma unroll
    for (int pass = 0; pass < 4; pass++) {
        int shift = 24 - 8*pass;
        for (int m = tid; m < NN; m += 256) {
            unsigned u = uv[m];
            bool cand = (pass == 0) || ((u >> (shift+8)) == (prefix >> (shift+8)));
            if (cand) atomicAdd(&hist[(u >> shift) & 255], 1u);
        }
        __syncthreads();
        if (tid < 32) {
            unsigned hv[8], loc[8];
            unsigned s = 0;
            #pragma unroll
            for (int i = 7; i >= 0; i--) {
                hv[i] = hist[lane*8 + i];
                s += hv[i];
                loc[i] = s;
            }
            unsigned run = s;
            #pragma unroll
            for (int o = 1; o < 32; o <<= 1) {
                unsigned t = __shfl_down_sync(0xffffffffu, run, o);
                if (lane + o < 32) run += t;
            }
            unsigned above = run - s;
            #pragma unroll
            for (int i = 0; i < 8; i++) {
                unsigned S  = above + loc[i];
                unsigned gt = S - hv[i];
                if ((unsigned)k <= S && (unsigned)k > gt) {
                    s_selb = lane*8 + i;
                    s_k    = k - (int)gt;
                }
            }
        }
        __syncthreads();
        prefix |= (unsigned)s_selb << shift;
        k = s_k;
        hist[tid] = 0;
        __syncthreads();
    }
    unsigned uT = prefix;
    int k_rem = k;
    if (tid == 0) s_nout = 0;
    __syncthreads();
    for (int m = tid; m < NN; m += 256) {
        if (uv[m] > uT) {
            int p = atomicAdd(&s_nout, 1);
            tk_s[p] = m;
        }
    }
    __syncthreads();
    int base = s_nout;
    const int CH = (NN + 255) / 256;
    int lo = tid * CH;
    int hi = lo + CH; if (hi > NN) hi = NN; if (lo > NN) lo = NN;
    int c_loc = 0;
    for (int m = lo; m < hi; m++) if (uv[m] == uT) c_loc++;
    int v = c_loc;
    #pragma unroll
    for (int o = 1; o < 32; o <<= 1) {
        int t = __shfl_up_sync(0xffffffffu, v, o);
        if (lane >= o) v += t;
    }
    if (lane == 31) warp_sums[w] = v;
    __syncthreads();
    int woff = 0;
    #pragma unroll
    for (int ww = 0; ww < 8; ww++) if (ww < w) woff += warp_sums[ww];
    int rank = woff + v - c_loc;
    for (int m = lo; m < hi; m++) {
        if (uv[m] == uT) {
            if (rank < k_rem) tk_s[base + rank] = m;
            rank++;
        }
    }
    __syncthreads();                   // uv dead after this barrier

    // ---- staging: K key-major, V d-major ----
    int bh = row / GG;
    int bi = bh / HH, h = bh % HH;
    const float* kb = &g_qkv[1][(size_t)bh*NN*DD];
    const float* vb = &g_qkv[2][(size_t)bh*NN*DD];
    for (int j = w; j < KT; j += 8) {
        int idx = tk_s[j];
        Kr[j][lane] = kb[(size_t)idx*DD + lane];
        Vt[lane][j] = vb[(size_t)idx*DD + lane];
    }
    __syncthreads();

    float* q4s = (float*)ublk + w*4*36;               // [4][36]
    float* p4s = (float*)(ublk + QS_BYTES) + w*4*100; // [4][100]
    const int* ql = &g_qlist[row*NN];
    const float* qb = &g_qkv[0][(size_t)bh*NN*DD];
    const float scale = 0.17677669529663687f;  // 32^-0.5

    for (int i0 = 0; i0 < cnt; i0 += 32) {
        int qbase = i0 + w*4;
        #pragma unroll
        for (int qq = 0; qq < 4; qq++) {
            int qi = qbase + qq;
            float val = 0.f;
            if (qi < cnt) val = qb[(size_t)ql[qi]*DD + lane];
            q4s[qq*36 + lane] = val;
        }
        __syncwarp();
        float s[4][3];
        #pragma unroll
        for (int qq = 0; qq < 4; qq++) { s[qq][0] = 0.f; s[qq][1] = 0.f; s[qq][2] = 0.f; }
        #pragma unroll
        for (int t = 0; t < 8; t++) {
            float4 k0 = *(const float4*)&Kr[lane     ][4*t];
            float4 k1 = *(const float4*)&Kr[lane + 32][4*t];
            float4 k2 = *(const float4*)&Kr[lane + 64][4*t];
            #pragma unroll
            for (int qq = 0; qq < 4; qq++) {
                float4 q4 = *(const float4*)&q4s[qq*36 + 4*t];
                s[qq][0] += q4.x*k0.x + q4.y*k0.y + q4.z*k0.z + q4.w*k0.w;
                s[qq][1] += q4.x*k1.x + q4.y*k1.y + q4.z*k1.z + q4.w*k1.w;
                s[qq][2] += q4.x*k2.x + q4.y*k2.y + q4.z*k2.z + q4.w*k2.w;
            }
        }
        float inv[4];
        #pragma unroll
        for (int qq = 0; qq < 4; qq++) {
            float s0 = s[qq][0]*scale, s1 = s[qq][1]*scale, s2 = s[qq][2]*scale;
            float mx = fmaxf(s0, fmaxf(s1, s2));
            #pragma unroll
            for (int o = 16; o; o >>= 1) mx = fmaxf(mx, __shfl_xor_sync(0xffffffffu, mx, o));
            float e0 = __expf(s0 - mx), e1 = __expf(s1 - mx), e2 = __expf(s2 - mx);
            float ps = e0 + e1 + e2;
            #pragma unroll
            for (int o = 16; o; o >>= 1) ps += __shfl_xor_sync(0xffffffffu, ps, o);
            inv[qq] = 1.f / ps;
            p4s[qq*100 + lane]      = e0;
            p4s[qq*100 + lane + 32] = e1;
            p4s[qq*100 + lane + 64] = e2;
        }
        __syncwarp();
        float a[4] = {0.f, 0.f, 0.f, 0.f};
        #pragma unroll
        for (int jj = 0; jj < KT/4; jj++) {
            float4 v4 = *(const float4*)&Vt[lane][4*jj];
            #pragma unroll
            for (int qq = 0; qq < 4; qq++) {
                float4 p4 = *(const float4*)&p4s[qq*100 + 4*jj];
                a[qq] += p4.x*v4.x + p4.y*v4.y + p4.z*v4.z + p4.w*v4.w;
            }
        }
        #pragma unroll
        for (int qq = 0; qq < 4; qq++) {
            int qi = qbase + qq;
            if (qi < cnt) {
                int n = ql[qi];
                g_att[(((size_t)bi*NN + n)*HH + h)*DD + lane] = a[qq] * inv[qq];
            }
        }
        __syncwarp();
    }
}

extern "C" void kernel_launch(void* const* d_in, const int* in_sizes, int n_in,
                              void* d_out, int out_size) {
    const float* x      = (const float*)d_in[0];
    const float* w_qkv  = (const float*)d_in[1];
    const float* w_gp   = (const float*)d_in[2];
    const float* w_proj = (const float*)d_in[3];
    float* out = (float*)d_out;

    gemm_tf32<0><<<dim3(9, 25), 256>>>(x, w_qkv, nullptr);       // QKV (+ zero-init)
    route_kernel<<<NQ/32, 256>>>(w_gp);
    qmw_score_kernel<<<dim3(25, BHc), 256>>>();
    select_attn_kernel<<<NROW, 256>>>();
    gemm_tf32<1><<<dim3(3, 25), 256>>>(nullptr, w_proj, out);    // proj: 3200x384x384
}